// round 16
// baseline (speedup 1.0000x reference)
#include <cuda_runtime.h>
#include <cuda_fp16.h>
#include <cstdint>

#define KDIM   256
#define BM     128
#define BN     256
#define BK     64

#define A_STAGE_BYTES (BM * BK * 2)            // 16384
#define A_TOTAL       (2 * A_STAGE_BYTES)      // 32768
#define B_CHUNK_BYTES (BN * BK * 2)            // 32768
#define B_TOTAL       (4 * B_CHUNK_BYTES)      // 131072
#define SMEM_TOTAL    (A_TOTAL + B_TOTAL)      // 163840

// ---------------- helpers ----------------
__device__ __forceinline__ uint32_t smem_u32(const void* p) {
    uint32_t a;
    asm("{ .reg .u64 t; cvta.to.shared.u64 t, %1; cvt.u32.u64 %0, t; }" : "=r"(a) : "l"(p));
    return a;
}
#define LDSM4(r0, r1, r2, r3, a)                                                 \
    asm volatile("ldmatrix.sync.aligned.m8n8.x4.shared.b16 {%0,%1,%2,%3}, [%4];" \
                 : "=r"(r0), "=r"(r1), "=r"(r2), "=r"(r3) : "r"(a))

__device__ __forceinline__ void mma_fp16(float* d, const uint32_t* a,
                                         uint32_t b0, uint32_t b1) {
    asm volatile(
        "mma.sync.aligned.m16n8k16.row.col.f32.f16.f16.f32 "
        "{%0,%1,%2,%3}, {%4,%5,%6,%7}, {%8,%9}, {%0,%1,%2,%3};"
        : "+f"(d[0]), "+f"(d[1]), "+f"(d[2]), "+f"(d[3])
        : "r"(a[0]), "r"(a[1]), "r"(a[2]), "r"(a[3]), "r"(b0), "r"(b1));
}

// ---------------- main GEMM: persistent CTAs, B resident (built in-kernel), 64x64 warp tile ----------------
__global__ __launch_bounds__(256, 1)
void cp2d_fp16_kernel(const float* __restrict__ x, const float* __restrict__ W,
                      float* __restrict__ out, int G, int NT) {
    extern __shared__ __align__(128) char smem[];
    const uint32_t sb = smem_u32(smem);

    const int tid  = threadIdx.x;
    const int lane = tid & 31;
    const int warp = tid >> 5;
    const int wm   = warp & 1;          // 2 warps along M (64 rows each)
    const int wn   = warp >> 1;         // 4 warps along N (64 cols each)
    const int bid  = blockIdx.x;

    const int my_tiles = (NT - bid + G - 1) / G;   // tiles: bid, bid+G, ...
    if (my_tiles <= 0) return;
    const int GG = my_tiles * 4;

    // A mapping: each thread owns 4 rows x one 16B fp16 unit (32B fp32)
    const int a_u   = tid & 7;          // 16B-unit index along k (fp32 k = a_u*8..+7)
    const int a_row = tid >> 3;         // base row (0..31), rows += j*32

    // ldmatrix per-lane invariants
    const int la_row = (lane & 7) + ((lane >> 3) & 1) * 8;
    const int la_u   = lane >> 4;
    const int lb_row = (lane & 7) + ((lane >> 4) & 1) * 8;
    const int lb_u   = (lane >> 3) & 1;

    // ---- build resident B directly from W (fp32 [K,N] -> fp16 Wt[N,K], swizzled) ----
    {
        const int n = (warp << 5) + lane;          // 0..255, one n-row per thread
        const uint32_t swn = (uint32_t)(n & 7) << 4;
#pragma unroll 1
        for (int c = 0; c < 4; c++) {
            const uint32_t bBase = sb + A_TOTAL + (uint32_t)c * B_CHUNK_BYTES + n * 128;
#pragma unroll
            for (int u = 0; u < 8; u++) {
                float v[8];
#pragma unroll
                for (int j = 0; j < 8; j++)        // coalesced: lanes = consecutive n
                    v[j] = W[(c * 64 + u * 8 + j) * KDIM + n];
                __half2 h0 = __floats2half2_rn(v[0], v[1]);
                __half2 h1 = __floats2half2_rn(v[2], v[3]);
                __half2 h2 = __floats2half2_rn(v[4], v[5]);
                __half2 h3 = __floats2half2_rn(v[6], v[7]);
                uint32_t addr = bBase + (((uint32_t)u << 4) ^ swn);
                asm volatile("st.shared.v4.b32 [%0], {%1, %2, %3, %4};"
                             :: "r"(addr), "r"(*(uint32_t*)&h0), "r"(*(uint32_t*)&h1),
                                "r"(*(uint32_t*)&h2), "r"(*(uint32_t*)&h3));
            }
        }
    }

    float acc[4][8][4];
#pragma unroll
    for (int mt = 0; mt < 4; mt++)
#pragma unroll
        for (int nt = 0; nt < 8; nt++)
#pragma unroll
            for (int i = 0; i < 4; i++) acc[mt][nt][i] = 0.f;

    float4 rA[8];     // 4 rows x 2 adjacent float4 (32B fp32 per row)

    auto m_of = [&](int gg) -> long {
        return ((long)bid + (long)(gg >> 2) * G) * BM;
    };
    auto ldgA = [&](int gg) {
        const long m0 = m_of(gg);
        const int k0 = (gg & 3) * BK + a_u * 8;
#pragma unroll
        for (int j = 0; j < 4; j++) {
            const float* p = x + (m0 + a_row + j * 32) * KDIM + k0;
            rA[j * 2 + 0] = *(const float4*)(p);
            rA[j * 2 + 1] = *(const float4*)(p + 4);
        }
    };
    auto stsA = [&](int st) {          // st = 0/1 ; one st.v4 per row
        const uint32_t aBase = sb + (uint32_t)st * A_STAGE_BYTES;
#pragma unroll
        for (int j = 0; j < 4; j++) {
            const int row = a_row + j * 32;
            uint32_t addr = aBase + row * 128 + ((a_u ^ (row & 7)) << 4);
            __half2 h0 = __floats2half2_rn(rA[j * 2].x,     rA[j * 2].y);
            __half2 h1 = __floats2half2_rn(rA[j * 2].z,     rA[j * 2].w);
            __half2 h2 = __floats2half2_rn(rA[j * 2 + 1].x, rA[j * 2 + 1].y);
            __half2 h3 = __floats2half2_rn(rA[j * 2 + 1].z, rA[j * 2 + 1].w);
            asm volatile("st.shared.v4.b32 [%0], {%1, %2, %3, %4};"
                         :: "r"(addr), "r"(*(uint32_t*)&h0), "r"(*(uint32_t*)&h1),
                            "r"(*(uint32_t*)&h2), "r"(*(uint32_t*)&h3));
        }
    };

    auto compute = [&](int st, int cb) {
        const uint32_t aBase = sb + (uint32_t)st * A_STAGE_BYTES;
        const uint32_t bBase = sb + A_TOTAL + (uint32_t)cb * B_CHUNK_BYTES;
#pragma unroll
        for (int ks = 0; ks < 4; ks++) {
            const int u0 = ks * 2;
            uint32_t b[4][4];
#pragma unroll
            for (int nt2 = 0; nt2 < 4; nt2++) {
                const int row = wn * 64 + nt2 * 16 + lb_row;
                uint32_t addr = bBase + row * 128 + (((u0 + lb_u) ^ (row & 7)) << 4);
                LDSM4(b[nt2][0], b[nt2][1], b[nt2][2], b[nt2][3], addr);
            }
#pragma unroll
            for (int mt = 0; mt < 4; mt++) {
                uint32_t a[4];
                const int row = wm * 64 + mt * 16 + la_row;
                uint32_t addr = aBase + row * 128 + (((u0 + la_u) ^ (row & 7)) << 4);
                LDSM4(a[0], a[1], a[2], a[3], addr);
#pragma unroll
                for (int nt2 = 0; nt2 < 4; nt2++)
#pragma unroll
                    for (int s = 0; s < 2; s++) {
                        const int nt = nt2 * 2 + s;
                        mma_fp16(acc[mt][nt], a, b[nt2][2 * s], b[nt2][2 * s + 1]);
                    }
            }
        }
    };

    // ---- prologue: stage A chunk 0 (B written above; sync covers both) ----
    ldgA(0);
    stsA(0);
    if (GG > 1) ldgA(1);
    __syncthreads();         // B + A stage0 visible

    // ---- unified chunk stream across all tiles ----
    for (int gg = 0; gg < GG; gg++) {
        const int st = gg & 1;
        if (gg + 1 < GG) {
            stsA(st ^ 1);                    // rA holds chunk gg+1
            if (gg + 2 < GG) ldgA(gg + 2);
        }
        compute(st, gg & 3);

        if ((gg & 3) == 3) {
            const long m0 = m_of(gg);
            const int er = lane >> 2;
            const int ec = (lane & 3) * 2;
#pragma unroll
            for (int mt = 0; mt < 4; mt++) {
                const long r0 = m0 + wm * 64 + mt * 16 + er;
#pragma unroll
                for (int nt = 0; nt < 8; nt++) {
                    const int col = wn * 64 + nt * 8 + ec;
                    *(float2*)(out + r0 * KDIM + col) =
                        make_float2(acc[mt][nt][0], acc[mt][nt][1]);
                    *(float2*)(out + (r0 + 8) * KDIM + col) =
                        make_float2(acc[mt][nt][2], acc[mt][nt][3]);
                }
            }
#pragma unroll
            for (int mt = 0; mt < 4; mt++)
#pragma unroll
                for (int nt = 0; nt < 8; nt++)
#pragma unroll
                    for (int i = 0; i < 4; i++) acc[mt][nt][i] = 0.f;
        }
        if (gg + 1 < GG) __syncthreads();    // stage (gg+1)&1 ready / WAR guard
    }
}

extern "C" void kernel_launch(void* const* d_in, const int* in_sizes, int n_in,
                              void* d_out, int out_size) {
    const float* x = (const float*)d_in[0];
    const float* W = (const float*)d_in[1];
    float* out = (float*)d_out;

    const int M  = in_sizes[0] / KDIM;   // 401408
    const int NT = M / BM;               // 3136 tiles

    int nsm = 0;
    cudaDeviceGetAttribute(&nsm, cudaDevAttrMultiProcessorCount, 0);
    if (nsm <= 0) nsm = 148;
    if (nsm > NT) nsm = NT;

    cudaFuncSetAttribute(cp2d_fp16_kernel,
                         cudaFuncAttributeMaxDynamicSharedMemorySize, SMEM_TOTAL);

    cp2d_fp16_kernel<<<nsm, 256, SMEM_TOTAL>>>(x, W, out, nsm, NT);
}